// round 9
// baseline (speedup 1.0000x reference)
#include <cuda_runtime.h>
#include <cstdint>

#define N_DOC   20000
#define N_WORD  80000
#define N_NODES 100000
#define HID     64
#define M_MASK  10000
#define E_EDGES 1000000

// ---------------- scratch (static __device__, allocation-free) ----------------
__device__ __align__(256) float g_xw1 [N_NODES * HID];  // x @ W1 (pre-aggregation)
__device__ __align__(256) float g_agg1[N_NODES * HID];  // layer1 neighbor sum
__device__ __align__(256) float g_h1  [N_NODES * HID];  // relu(layer1)
__device__ __align__(256) float g_xw2 [N_NODES * HID];  // h1 @ W2
__device__ __align__(256) float g_agg2[N_NODES * HID];  // layer2 neighbor sum
__device__ __align__(256) float g_deg [N_NODES];
__device__ __align__(256) float g_dis [N_NODES];
__device__ __align__(256) float g_Weff[300 * HID];      // W_lin @ W1
__device__ __align__(256) float g_bword[HID];           // b_lin @ W1
__device__ unsigned char g_maskflag[N_NODES];
__device__ int g_mcount;                                 // # masked-dst edges
__device__ int g_medges[E_EDGES];                        // compacted edge ids

// ---------------- init: zero accumulators, deg=1 (self loop), flags=0 ---------
__global__ void init_kernel() {
    int idx = blockIdx.x * blockDim.x + threadIdx.x;
    if (idx < N_NODES * HID) {
        g_agg1[idx] = 0.f;
        g_agg2[idx] = 0.f;
    }
    if (idx < N_NODES) {
        g_deg[idx] = 1.0f;      // self-loop weight
        g_maskflag[idx] = 0;
    }
    if (idx == 0) g_mcount = 0;
}

__global__ void mask_set_kernel(const int* __restrict__ mask_idx) {
    int idx = blockIdx.x * blockDim.x + threadIdx.x;
    if (idx < M_MASK) {
        unsigned n = (unsigned)mask_idx[idx];
        if (n < N_NODES) g_maskflag[n] = 1;
    }
}

// ---------------- degree accumulation + masked-edge compaction ----------------
__global__ void deg_compact_kernel(const int* __restrict__ cols,
                                   const float* __restrict__ w, int E) {
    __shared__ int s_cnt, s_base;
    if (threadIdx.x == 0) s_cnt = 0;
    __syncthreads();
    int idx = blockIdx.x * blockDim.x + threadIdx.x;
    int slot = -1;
    if (idx < E) {
        unsigned c = (unsigned)cols[idx];
        if (c < N_NODES) {
            atomicAdd(&g_deg[c], w[idx]);
            if (g_maskflag[c]) slot = atomicAdd(&s_cnt, 1);
        }
    }
    __syncthreads();
    if (threadIdx.x == 0) s_base = atomicAdd(&g_mcount, s_cnt);
    __syncthreads();
    if (slot >= 0) g_medges[s_base + slot] = idx;
}

__global__ void dis_kernel() {
    int idx = blockIdx.x * blockDim.x + threadIdx.x;
    if (idx < N_NODES) g_dis[idx] = rsqrtf(g_deg[idx]);   // deg >= 1 always
}

// ---------------- W_eff = W_lin @ W1 ; b_word = b_lin @ W1 --------------------
__global__ void weff_kernel(const float* __restrict__ W_lin,
                            const float* __restrict__ W1,
                            const float* __restrict__ b_lin) {
    int tid = blockIdx.x * blockDim.x + threadIdx.x;
    if (tid < 300 * HID) {
        int n = tid & 63, r = tid >> 6;
        float s = 0.f;
        #pragma unroll 8
        for (int k = 0; k < 768; k++) s += W_lin[r * 768 + k] * W1[k * 64 + n];
        g_Weff[tid] = s;
    } else if (tid < 301 * HID) {
        int n = tid & 63;
        float s = 0.f;
        #pragma unroll 8
        for (int k = 0; k < 768; k++) s += b_lin[k] * W1[k * 64 + n];
        g_bword[n] = s;
    }
}

// ---------------- GEMM: C[M,64] = A[M,K] @ B[K,64] (+bias) --------------------
// BM=128, BN=64, BK=16, 256 threads, 8 rows x 4 cols per thread.
// Inner product uses packed fp32 FFMA2 (fma.rn.f32x2, sm_100+): accumulators
// packed along the column axis (2 cols per 64-bit reg) -> 16 FFMA2/k instead
// of 32 FFMA/k. A tile stored DUPLICATED in smem so the (a,a) broadcast
// operand is one conflict-free LDS.64.
__global__ __launch_bounds__(256)
void gemm64_kernel(const float* __restrict__ Ap,
                   const float* __restrict__ Bp,
                   int a_sel, int b_sel, int bias_sel, int c_sel,
                   long long c_off, int M, int K) {
    const int BM = 128, BK = 16;
    __shared__ float As2[BK][2 * BM];   // [k][2m] = [k][2m+1] = A[m][k]
    __shared__ float Bs[BK][64];
    const float* A = a_sel ? g_h1 : Ap;
    const float* B = b_sel ? g_Weff : Bp;
    float* C = (c_sel ? g_xw2 : g_xw1) + c_off;

    int tid  = threadIdx.x;
    int bm   = blockIdx.x * BM;
    int trow = tid >> 4;        // 0..15 -> rows trow*8..+7
    int tcol = tid & 15;        // 0..15 -> cols tcol*4..+3

    unsigned long long acc[8][2];   // 8 rows x (2 col-pairs)
    #pragma unroll
    for (int i = 0; i < 8; i++) { acc[i][0] = 0ull; acc[i][1] = 0ull; }

    for (int k0 = 0; k0 < K; k0 += BK) {
        #pragma unroll
        for (int i = 0; i < 8; i++) {
            int idx = tid + i * 256;
            int m = idx >> 4, k = idx & 15;
            int gm = bm + m, gk = k0 + k;
            float v = 0.f;
            if (gm < M && gk < K) v = A[(size_t)gm * K + gk];
            float2 d; d.x = v; d.y = v;
            *(float2*)&As2[k][2 * m] = d;   // duplicated pair, 8B-aligned
        }
        #pragma unroll
        for (int i = 0; i < 4; i++) {
            int idx = tid + i * 256;
            int k = idx >> 6, n = idx & 63;
            int gk = k0 + k;
            Bs[k][n] = (gk < K) ? B[gk * 64 + n] : 0.f;
        }
        __syncthreads();
        #pragma unroll
        for (int k = 0; k < BK; k++) {
            float4 bv = *(const float4*)&Bs[k][tcol * 4];
            unsigned long long b01, b23;
            asm("mov.b64 %0, {%1, %2};" : "=l"(b01) : "f"(bv.x), "f"(bv.y));
            asm("mov.b64 %0, {%1, %2};" : "=l"(b23) : "f"(bv.z), "f"(bv.w));
            #pragma unroll
            for (int i = 0; i < 8; i++) {
                unsigned long long aa =
                    *(const unsigned long long*)&As2[k][2 * (trow * 8 + i)];
                asm("fma.rn.f32x2 %0, %1, %2, %0;" : "+l"(acc[i][0])
                    : "l"(aa), "l"(b01));
                asm("fma.rn.f32x2 %0, %1, %2, %0;" : "+l"(acc[i][1])
                    : "l"(aa), "l"(b23));
            }
        }
        __syncthreads();
    }
    #pragma unroll
    for (int i = 0; i < 8; i++) {
        int gm = bm + trow * 8 + i;
        if (gm < M) {
            float4 r;
            asm("mov.b64 {%0, %1}, %2;" : "=f"(r.x), "=f"(r.y) : "l"(acc[i][0]));
            asm("mov.b64 {%0, %1}, %2;" : "=f"(r.z), "=f"(r.w) : "l"(acc[i][1]));
            int n = tcol * 4;
            if (bias_sel) {
                r.x += g_bword[n]; r.y += g_bword[n + 1];
                r.z += g_bword[n + 2]; r.w += g_bword[n + 3];
            }
            *(float4*)&C[(size_t)gm * 64 + n] = r;
        }
    }
}

// ---------------- layer-1 scatter: agg1[col] += coef * xw1[row] ---------------
// Half-warp per edge; lane sub handles features 4*sub..4*sub+3 via float4
// gather + one red.global.add.v4.f32 (16 vector REDs per edge).
__global__ void scatter1_kernel(const int* __restrict__ rows,
                                const int* __restrict__ cols,
                                const float* __restrict__ w, int E) {
    int hw  = (blockIdx.x * blockDim.x + threadIdx.x) >> 4;   // edge id
    int sub = threadIdx.x & 15;
    if (hw >= E) return;
    unsigned c = (unsigned)cols[hw];
    if (c >= N_NODES) return;
    unsigned r = (unsigned)rows[hw];
    if (r >= N_NODES) return;
    float coef = g_dis[r] * w[hw] * g_dis[c];
    float4 v = *(const float4*)(g_xw1 + (size_t)r * 64 + sub * 4);
    v.x *= coef; v.y *= coef; v.z *= coef; v.w *= coef;
    float* dst = g_agg1 + (size_t)c * 64 + sub * 4;
    asm volatile("red.global.add.v4.f32 [%0], {%1, %2, %3, %4};"
                 :: "l"(dst), "f"(v.x), "f"(v.y), "f"(v.z), "f"(v.w) : "memory");
}

// ---------------- layer-2 scatter over compacted masked-dst edges -------------
__global__ void scatter2_kernel(const int* __restrict__ rows,
                                const int* __restrict__ cols,
                                const float* __restrict__ w) {
    int nhw = (gridDim.x * blockDim.x) >> 4;
    int hw0 = (blockIdx.x * blockDim.x + threadIdx.x) >> 4;
    int sub = threadIdx.x & 15;
    int cnt = g_mcount;
    for (int i = hw0; i < cnt; i += nhw) {
        int e = g_medges[i];
        unsigned c = (unsigned)cols[e];
        unsigned r = (unsigned)rows[e];
        if (c >= N_NODES || r >= N_NODES) continue;
        float coef = g_dis[r] * w[e] * g_dis[c];
        float4 v = *(const float4*)(g_xw2 + (size_t)r * 64 + sub * 4);
        v.x *= coef; v.y *= coef; v.z *= coef; v.w *= coef;
        float* dst = g_agg2 + (size_t)c * 64 + sub * 4;
        asm volatile("red.global.add.v4.f32 [%0], {%1, %2, %3, %4};"
                     :: "l"(dst), "f"(v.x), "f"(v.y), "f"(v.z), "f"(v.w) : "memory");
    }
}

// ---------------- h1 = relu(agg1 + dis^2 * xw1 + b1)  (self-loop folded) ------
__global__ void relu_combine_kernel(const float* __restrict__ b1) {
    int idx = blockIdx.x * blockDim.x + threadIdx.x;
    if (idx < N_NODES * HID) {
        int i = idx >> 6, j = idx & 63;
        float d = g_dis[i];
        float v = g_agg1[idx] + d * d * g_xw1[idx] + b1[j];
        g_h1[idx] = v > 0.f ? v : 0.f;
    }
}

// ---------------- final: out = agg2[node] + dis^2*xw2[node] + b2, gather y ----
__global__ void final_kernel(const int* __restrict__ mask_idx,
                             const int* __restrict__ y,
                             const float* __restrict__ b2,
                             float* __restrict__ out, int write_y) {
    int idx = blockIdx.x * blockDim.x + threadIdx.x;
    if (idx < M_MASK * HID) {
        int i = idx >> 6, j = idx & 63;
        unsigned node = (unsigned)mask_idx[i];
        if (node < N_NODES) {
            float d = g_dis[node];
            out[idx] = g_agg2[(size_t)node * 64 + j]
                     + d * d * g_xw2[(size_t)node * 64 + j] + b2[j];
        } else {
            out[idx] = 0.f;
        }
    }
    if (write_y && idx < M_MASK) {
        unsigned node = (unsigned)mask_idx[idx];
        out[M_MASK * HID + idx] = (node < N_NODES) ? (float)y[node] : 0.f;
    }
}

// ---------------- launch ------------------------------------------------------
extern "C" void kernel_launch(void* const* d_in, const int* in_sizes, int n_in,
                              void* d_out, int out_size) {
    const float *doc = nullptr, *word = nullptr, *ew = nullptr;
    const float *W_lin = nullptr, *b_lin = nullptr, *W1 = nullptr, *b1 = nullptr;
    const float *b2 = nullptr, *W2 = nullptr;
    const int *edge_index = nullptr, *mask_idx = nullptr, *yv = nullptr;  // int32
    for (int i = 0; i < n_in; i++) {
        switch (in_sizes[i]) {
            case N_DOC * 768:       doc       = (const float*)d_in[i]; break;
            case N_WORD * 300:      word      = (const float*)d_in[i]; break;
            case E_EDGES:           ew        = (const float*)d_in[i]; break;
            case 300 * 768:         W_lin     = (const float*)d_in[i]; break;
            case 768:               b_lin     = (const float*)d_in[i]; break;
            case 768 * HID:         W1        = (const float*)d_in[i]; break;
            case HID * HID:         W2        = (const float*)d_in[i]; break;
            case 2 * E_EDGES:       edge_index= (const int*)d_in[i]; break;
            case M_MASK:            mask_idx  = (const int*)d_in[i]; break;
            case N_NODES:           yv        = (const int*)d_in[i]; break;
            case HID:               if (!b1) b1 = (const float*)d_in[i];   // W1,b1 precede W2,b2
                                    else     b2 = (const float*)d_in[i]; break;
            default: break;
        }
    }
    const int E = E_EDGES;
    const int* rows = edge_index;       // edge_index[0]
    const int* cols = edge_index + E;   // edge_index[1]

    float* out = (float*)d_out;
    int write_y = (out_size >= M_MASK * HID + M_MASK) ? 1 : 0;

    const int T = 256;
    // 1) init accumulators / deg / flags / counter
    init_kernel<<<(N_NODES * HID + T - 1) / T, T>>>();
    // 2) mask flags (must precede deg_compact)
    mask_set_kernel<<<(M_MASK + T - 1) / T, T>>>(mask_idx);
    // 3) fused weight W_eff = W_lin@W1, b_word = b_lin@W1
    weff_kernel<<<(301 * HID + T - 1) / T, T>>>(W_lin, W1, b_lin);
    // 4) degree + masked-edge compaction + normalization
    deg_compact_kernel<<<(E + T - 1) / T, T>>>(cols, ew, E);
    dis_kernel<<<(N_NODES + T - 1) / T, T>>>();
    // 5) xw1: doc part = doc@W1 ; word part = word@W_eff + b_word
    gemm64_kernel<<<(N_DOC + 127) / 128, 256>>>(doc, W1, 0, 0, 0, 0,
                                                0, N_DOC, 768);
    gemm64_kernel<<<(N_WORD + 127) / 128, 256>>>(word, nullptr, 0, 1, 1, 0,
                                                 (long long)N_DOC * HID, N_WORD, 300);
    // 6) layer-1 aggregation: half-warp per edge, vector REDs
    {
        int edges_per_block = T / 16;  // 16
        scatter1_kernel<<<(E + edges_per_block - 1) / edges_per_block, T>>>(
            rows, cols, ew, E);
    }
    relu_combine_kernel<<<(N_NODES * HID + T - 1) / T, T>>>(b1);
    // 7) layer 2
    gemm64_kernel<<<(N_NODES + 127) / 128, 256>>>(nullptr, W2, 1, 0, 0, 1,
                                                  0, N_NODES, 64);
    scatter2_kernel<<<1024, T>>>(rows, cols, ew);
    // 8) output gather
    final_kernel<<<(M_MASK * HID + T - 1) / T, T>>>(mask_idx, yv, b2, out, write_y);
}

// round 10
// speedup vs baseline: 1.6006x; 1.6006x over previous
#include <cuda_runtime.h>
#include <cstdint>

#define N_DOC   20000
#define N_WORD  80000
#define N_NODES 100000
#define HID     64
#define M_MASK  10000
#define E_EDGES 1000000

// ---------------- scratch (static __device__, allocation-free) ----------------
__device__ __align__(256) float g_xw1 [N_NODES * HID];  // x @ W1 (pre-aggregation)
__device__ __align__(256) float g_agg1[N_NODES * HID];  // layer1 neighbor sum
__device__ __align__(256) float g_h1  [N_NODES * HID];  // relu(layer1)
__device__ __align__(256) float g_xw2 [N_NODES * HID];  // h1 @ W2
__device__ __align__(256) float g_agg2[N_NODES * HID];  // layer2 neighbor sum
__device__ __align__(256) float g_deg [N_NODES];
__device__ __align__(256) float g_dis [N_NODES];
__device__ __align__(256) float g_Weff[300 * HID];      // W_lin @ W1
__device__ __align__(256) float g_bword[HID];           // b_lin @ W1
__device__ unsigned char g_maskflag[N_NODES];
__device__ int g_mcount;                                 // # masked-dst edges
__device__ int g_medges[E_EDGES];                        // compacted edge ids

// ---------------- init: zero accumulators, deg=1 (self loop), flags=0 ---------
__global__ void init_kernel() {
    int idx = blockIdx.x * blockDim.x + threadIdx.x;
    if (idx < N_NODES * HID) {
        g_agg1[idx] = 0.f;
        g_agg2[idx] = 0.f;
    }
    if (idx < N_NODES) {
        g_deg[idx] = 1.0f;      // self-loop weight
        g_maskflag[idx] = 0;
    }
    if (idx == 0) g_mcount = 0;
}

__global__ void mask_set_kernel(const int* __restrict__ mask_idx) {
    int idx = blockIdx.x * blockDim.x + threadIdx.x;
    if (idx < M_MASK) {
        unsigned n = (unsigned)mask_idx[idx];
        if (n < N_NODES) g_maskflag[n] = 1;
    }
}

// ---------------- degree accumulation + masked-edge compaction ----------------
__global__ void deg_compact_kernel(const int* __restrict__ cols,
                                   const float* __restrict__ w, int E) {
    __shared__ int s_cnt, s_base;
    if (threadIdx.x == 0) s_cnt = 0;
    __syncthreads();
    int idx = blockIdx.x * blockDim.x + threadIdx.x;
    int slot = -1;
    if (idx < E) {
        unsigned c = (unsigned)cols[idx];
        if (c < N_NODES) {
            atomicAdd(&g_deg[c], w[idx]);
            if (g_maskflag[c]) slot = atomicAdd(&s_cnt, 1);
        }
    }
    __syncthreads();
    if (threadIdx.x == 0) s_base = atomicAdd(&g_mcount, s_cnt);
    __syncthreads();
    if (slot >= 0) g_medges[s_base + slot] = idx;
}

__global__ void dis_kernel() {
    int idx = blockIdx.x * blockDim.x + threadIdx.x;
    if (idx < N_NODES) g_dis[idx] = rsqrtf(g_deg[idx]);   // deg >= 1 always
}

// ---------------- W_eff = W_lin @ W1 ; b_word = b_lin @ W1 --------------------
__global__ void weff_kernel(const float* __restrict__ W_lin,
                            const float* __restrict__ W1,
                            const float* __restrict__ b_lin) {
    int tid = blockIdx.x * blockDim.x + threadIdx.x;
    if (tid < 300 * HID) {
        int n = tid & 63, r = tid >> 6;
        float s = 0.f;
        #pragma unroll 8
        for (int k = 0; k < 768; k++) s += W_lin[r * 768 + k] * W1[k * 64 + n];
        g_Weff[tid] = s;
    } else if (tid < 301 * HID) {
        int n = tid & 63;
        float s = 0.f;
        #pragma unroll 8
        for (int k = 0; k < 768; k++) s += b_lin[k] * W1[k * 64 + n];
        g_bword[n] = s;
    }
}

// ---------------- GEMM: C[M,64] = A[M,K] @ B[K,64] (+bias) --------------------
// BM=128, BN=64, BK=16, 256 threads, 8 rows x 4 cols per thread (plain FFMA —
// the R9 FFMA2 experiment regressed and is reverted).
// Global loads vectorized: A tile = 2x LDG.128 per thread (scalar fallback on
// the K-tail tile), B tile = 1x LDG.128 + STS.128 per thread.
__global__ __launch_bounds__(256)
void gemm64_kernel(const float* __restrict__ Ap,
                   const float* __restrict__ Bp,
                   int a_sel, int b_sel, int bias_sel, int c_sel,
                   long long c_off, int M, int K) {
    const int BM = 128, BK = 16;
    __shared__ float As[BK][BM + 4];
    __shared__ float Bs[BK][64];
    const float* A = a_sel ? g_h1 : Ap;
    const float* B = b_sel ? g_Weff : Bp;
    float* C = (c_sel ? g_xw2 : g_xw1) + c_off;

    int tid  = threadIdx.x;
    int bm   = blockIdx.x * BM;
    int trow = tid >> 4;        // 0..15
    int tcol = tid & 15;        // 0..15

    // A-load mapping: thread -> (row am, k-half akq)
    int am  = tid >> 1;         // 0..127
    int akq = (tid & 1) * 8;    // 0 or 8
    // B-load mapping: thread -> (k bk, col bn)
    int bk  = tid >> 4;         // 0..15
    int bn  = (tid & 15) * 4;   // 0..60

    float acc[8][4];
    #pragma unroll
    for (int i = 0; i < 8; i++)
        #pragma unroll
        for (int j = 0; j < 4; j++) acc[i][j] = 0.f;

    for (int k0 = 0; k0 < K; k0 += BK) {
        // ---- A tile: rows bm..bm+127, cols k0..k0+15 ----
        {
            int gm = bm + am;
            float v[8];
            if (gm < M && k0 + BK <= K) {
                const float* src = A + (size_t)gm * K + k0 + akq;
                float4 v0 = *(const float4*)src;
                float4 v1 = *(const float4*)(src + 4);
                v[0] = v0.x; v[1] = v0.y; v[2] = v0.z; v[3] = v0.w;
                v[4] = v1.x; v[5] = v1.y; v[6] = v1.z; v[7] = v1.w;
            } else {
                #pragma unroll
                for (int j = 0; j < 8; j++) {
                    int gk = k0 + akq + j;
                    v[j] = (gm < M && gk < K) ? A[(size_t)gm * K + gk] : 0.f;
                }
            }
            #pragma unroll
            for (int j = 0; j < 8; j++) As[akq + j][am] = v[j];
        }
        // ---- B tile: rows k0..k0+15, 64 cols ----
        {
            int gk = k0 + bk;
            float4 bv = make_float4(0.f, 0.f, 0.f, 0.f);
            if (gk < K) bv = *(const float4*)&B[gk * 64 + bn];
            *(float4*)&Bs[bk][bn] = bv;
        }
        __syncthreads();
        #pragma unroll
        for (int k = 0; k < BK; k++) {
            float4 a0 = *(const float4*)&As[k][trow * 8];
            float4 a1 = *(const float4*)&As[k][trow * 8 + 4];
            float4 bv = *(const float4*)&Bs[k][tcol * 4];
            float a[8] = {a0.x, a0.y, a0.z, a0.w, a1.x, a1.y, a1.z, a1.w};
            float b[4] = {bv.x, bv.y, bv.z, bv.w};
            #pragma unroll
            for (int i = 0; i < 8; i++)
                #pragma unroll
                for (int j = 0; j < 4; j++) acc[i][j] += a[i] * b[j];
        }
        __syncthreads();
    }
    #pragma unroll
    for (int i = 0; i < 8; i++) {
        int gm = bm + trow * 8 + i;
        if (gm < M) {
            int n = tcol * 4;
            float4 r;
            r.x = acc[i][0]; r.y = acc[i][1]; r.z = acc[i][2]; r.w = acc[i][3];
            if (bias_sel) {
                r.x += g_bword[n]; r.y += g_bword[n + 1];
                r.z += g_bword[n + 2]; r.w += g_bword[n + 3];
            }
            *(float4*)&C[(size_t)gm * 64 + n] = r;
        }
    }
}

// ---------------- layer-1 scatter: agg1[col] += coef * xw1[row] ---------------
// Half-warp per edge; lane sub handles features 4*sub..4*sub+3 via float4
// gather + one red.global.add.v4.f32 (16 vector REDs per edge).
__global__ void scatter1_kernel(const int* __restrict__ rows,
                                const int* __restrict__ cols,
                                const float* __restrict__ w, int E) {
    int hw  = (blockIdx.x * blockDim.x + threadIdx.x) >> 4;   // edge id
    int sub = threadIdx.x & 15;
    if (hw >= E) return;
    unsigned c = (unsigned)cols[hw];
    if (c >= N_NODES) return;
    unsigned r = (unsigned)rows[hw];
    if (r >= N_NODES) return;
    float coef = g_dis[r] * w[hw] * g_dis[c];
    float4 v = *(const float4*)(g_xw1 + (size_t)r * 64 + sub * 4);
    v.x *= coef; v.y *= coef; v.z *= coef; v.w *= coef;
    float* dst = g_agg1 + (size_t)c * 64 + sub * 4;
    asm volatile("red.global.add.v4.f32 [%0], {%1, %2, %3, %4};"
                 :: "l"(dst), "f"(v.x), "f"(v.y), "f"(v.z), "f"(v.w) : "memory");
}

// ---------------- layer-2 scatter over compacted masked-dst edges -------------
__global__ void scatter2_kernel(const int* __restrict__ rows,
                                const int* __restrict__ cols,
                                const float* __restrict__ w) {
    int nhw = (gridDim.x * blockDim.x) >> 4;
    int hw0 = (blockIdx.x * blockDim.x + threadIdx.x) >> 4;
    int sub = threadIdx.x & 15;
    int cnt = g_mcount;
    for (int i = hw0; i < cnt; i += nhw) {
        int e = g_medges[i];
        unsigned c = (unsigned)cols[e];
        unsigned r = (unsigned)rows[e];
        if (c >= N_NODES || r >= N_NODES) continue;
        float coef = g_dis[r] * w[e] * g_dis[c];
        float4 v = *(const float4*)(g_xw2 + (size_t)r * 64 + sub * 4);
        v.x *= coef; v.y *= coef; v.z *= coef; v.w *= coef;
        float* dst = g_agg2 + (size_t)c * 64 + sub * 4;
        asm volatile("red.global.add.v4.f32 [%0], {%1, %2, %3, %4};"
                     :: "l"(dst), "f"(v.x), "f"(v.y), "f"(v.z), "f"(v.w) : "memory");
    }
}

// ---------------- h1 = relu(agg1 + dis^2 * xw1 + b1)  (self-loop folded) ------
__global__ void relu_combine_kernel(const float* __restrict__ b1) {
    int idx = blockIdx.x * blockDim.x + threadIdx.x;
    if (idx < N_NODES * HID) {
        int i = idx >> 6, j = idx & 63;
        float d = g_dis[i];
        float v = g_agg1[idx] + d * d * g_xw1[idx] + b1[j];
        g_h1[idx] = v > 0.f ? v : 0.f;
    }
}

// ---------------- final: out = agg2[node] + dis^2*xw2[node] + b2, gather y ----
__global__ void final_kernel(const int* __restrict__ mask_idx,
                             const int* __restrict__ y,
                             const float* __restrict__ b2,
                             float* __restrict__ out, int write_y) {
    int idx = blockIdx.x * blockDim.x + threadIdx.x;
    if (idx < M_MASK * HID) {
        int i = idx >> 6, j = idx & 63;
        unsigned node = (unsigned)mask_idx[i];
        if (node < N_NODES) {
            float d = g_dis[node];
            out[idx] = g_agg2[(size_t)node * 64 + j]
                     + d * d * g_xw2[(size_t)node * 64 + j] + b2[j];
        } else {
            out[idx] = 0.f;
        }
    }
    if (write_y && idx < M_MASK) {
        unsigned node = (unsigned)mask_idx[idx];
        out[M_MASK * HID + idx] = (node < N_NODES) ? (float)y[node] : 0.f;
    }
}

// ---------------- launch ------------------------------------------------------
extern "C" void kernel_launch(void* const* d_in, const int* in_sizes, int n_in,
                              void* d_out, int out_size) {
    const float *doc = nullptr, *word = nullptr, *ew = nullptr;
    const float *W_lin = nullptr, *b_lin = nullptr, *W1 = nullptr, *b1 = nullptr;
    const float *b2 = nullptr, *W2 = nullptr;
    const int *edge_index = nullptr, *mask_idx = nullptr, *yv = nullptr;  // int32
    for (int i = 0; i < n_in; i++) {
        switch (in_sizes[i]) {
            case N_DOC * 768:       doc       = (const float*)d_in[i]; break;
            case N_WORD * 300:      word      = (const float*)d_in[i]; break;
            case E_EDGES:           ew        = (const float*)d_in[i]; break;
            case 300 * 768:         W_lin     = (const float*)d_in[i]; break;
            case 768:               b_lin     = (const float*)d_in[i]; break;
            case 768 * HID:         W1        = (const float*)d_in[i]; break;
            case HID * HID:         W2        = (const float*)d_in[i]; break;
            case 2 * E_EDGES:       edge_index= (const int*)d_in[i]; break;
            case M_MASK:            mask_idx  = (const int*)d_in[i]; break;
            case N_NODES:           yv        = (const int*)d_in[i]; break;
            case HID:               if (!b1) b1 = (const float*)d_in[i];   // W1,b1 precede W2,b2
                                    else     b2 = (const float*)d_in[i]; break;
            default: break;
        }
    }
    const int E = E_EDGES;
    const int* rows = edge_index;       // edge_index[0]
    const int* cols = edge_index + E;   // edge_index[1]

    float* out = (float*)d_out;
    int write_y = (out_size >= M_MASK * HID + M_MASK) ? 1 : 0;

    const int T = 256;
    // 1) init accumulators / deg / flags / counter
    init_kernel<<<(N_NODES * HID + T - 1) / T, T>>>();
    // 2) mask flags (must precede deg_compact)
    mask_set_kernel<<<(M_MASK + T - 1) / T, T>>>(mask_idx);
    // 3) fused weight W_eff = W_lin@W1, b_word = b_lin@W1
    weff_kernel<<<(301 * HID + T - 1) / T, T>>>(W_lin, W1, b_lin);
    // 4) degree + masked-edge compaction + normalization
    deg_compact_kernel<<<(E + T - 1) / T, T>>>(cols, ew, E);
    dis_kernel<<<(N_NODES + T - 1) / T, T>>>();
    // 5) xw1: doc part = doc@W1 ; word part = word@W_eff + b_word
    gemm64_kernel<<<(N_DOC + 127) / 128, 256>>>(doc, W1, 0, 0, 0, 0,
                                                0, N_DOC, 768);
    gemm64_kernel<<<(N_WORD + 127) / 128, 256>>>(word, nullptr, 0, 1, 1, 0,
                                                 (long long)N_DOC * HID, N_WORD, 300);
    // 6) layer-1 aggregation: half-warp per edge, vector REDs
    {
        int edges_per_block = T / 16;  // 16
        scatter1_kernel<<<(E + edges_per_block - 1) / edges_per_block, T>>>(
            rows, cols, ew, E);
    }
    relu_combine_kernel<<<(N_NODES * HID + T - 1) / T, T>>>(b1);
    // 7) layer 2
    gemm64_kernel<<<(N_NODES + 127) / 128, 256>>>(nullptr, W2, 1, 0, 0, 1,
                                                  0, N_NODES, 64);
    scatter2_kernel<<<1024, T>>>(rows, cols, ew);
    // 8) output gather
    final_kernel<<<(M_MASK * HID + T - 1) / T, T>>>(mask_idx, yv, b2, out, write_y);
}